// round 6
// baseline (speedup 1.0000x reference)
#include <cuda_runtime.h>
#include <math.h>
#include <stdint.h>

// ---------------------------------------------------------------------------
// Round 6: tcgen05 unavailable in this toolchain (compute_103 PTX target), so
// optimize the SIMT path. Phase 1 (SMEM-table gather) unchanged. Phase 2: one
// point per thread, __launch_bounds__(128,4) to force <=128 regs -> 16
// warps/SM, doubling latency-hiding for the FFMA2-bound MLP.
// ---------------------------------------------------------------------------

namespace {

constexpr int L_LEVELS = 16;
constexpr int T_SIZE   = 16384;
constexpr int B_MAX    = 1 << 21;
constexpr int P1_THREADS = 1024;
constexpr int P1_PTS_PER_BLOCK = 16384;
constexpr int P2_THREADS = 128;

typedef unsigned long long u64;

struct NsParams { int ns[L_LEVELS]; };

__device__ float2 g_feats[(size_t)L_LEVELS * B_MAX];   // 256 MB scratch

__device__ __forceinline__ void fma2(u64& d, u64 a, u64 b) {
    asm("fma.rn.f32x2 %0, %1, %2, %0;" : "+l"(d) : "l"(a), "l"(b));
}
__device__ __forceinline__ u64 pack2(float lo, float hi) {
    u64 r; asm("mov.b64 %0, {%1, %2};" : "=l"(r) : "f"(lo), "f"(hi)); return r;
}
__device__ __forceinline__ float2 unpack2(u64 v) {
    float2 r; asm("mov.b64 {%0, %1}, %2;" : "=f"(r.x), "=f"(r.y) : "l"(v)); return r;
}
__device__ __forceinline__ float sigmoidf_fast(float v) {
    return 1.0f / (1.0f + __expf(-v));
}
__device__ __forceinline__ ulonglong2 lds128(const float* p) {
    ulonglong2 v;
    asm("ld.shared.v2.u64 {%0, %1}, [%2];"
        : "=l"(v.x), "=l"(v.y) : "l"(__cvta_generic_to_shared(p)));
    return v;
}

// ============================ Phase 1: gather ==============================
__global__ __launch_bounds__(P1_THREADS, 1)
void gather_kernel(const float* __restrict__ x,
                   const float* __restrict__ embed,
                   int B, NsParams nsp)
{
    extern __shared__ float2 stab[];   // T_SIZE float2 = 128 KB

    const int l = blockIdx.y;
    const int n = nsp.ns[l];
    const float nf = (float)n;
    const int np1 = n + 1;
    const bool dense = (np1 * np1 * np1 <= T_SIZE);

    {
        const float4* src = reinterpret_cast<const float4*>(embed) + (size_t)l * (T_SIZE / 2);
        float4* dst = reinterpret_cast<float4*>(stab);
        for (int i = threadIdx.x; i < T_SIZE / 2; i += P1_THREADS) dst[i] = src[i];
    }
    __syncthreads();

    const int base = blockIdx.x * P1_PTS_PER_BLOCK;
    const int end  = min(base + P1_PTS_PER_BLOCK, B);
    float2* featl = g_feats + (size_t)l * B;

    for (int p = base + threadIdx.x; p < end; p += P1_THREADS) {
        const float2* xv = reinterpret_cast<const float2*>(x) + (size_t)p * 3;
        const float2 a0 = __ldg(&xv[0]);
        const float2 a1 = __ldg(&xv[1]);

        float px = fminf(fmaxf((a0.x + 5.0f) * 0.1f, 0.0f), 0.999999f);
        float py = fminf(fmaxf((a0.y + 5.0f) * 0.1f, 0.0f), 0.999999f);
        float pz = fminf(fmaxf((a1.x + 5.0f) * 0.1f, 0.0f), 0.999999f);

        const float xl0 = px * nf, xl1 = py * nf, xl2 = pz * nf;
        const float f0 = floorf(xl0), f1 = floorf(xl1), f2 = floorf(xl2);
        const float w0 = xl0 - f0, w1 = xl1 - f1, w2 = xl2 - f2;
        const float u0 = 1.0f - w0, u1 = 1.0f - w1, u2 = 1.0f - w2;
        const int v0 = (int)f0, v1 = (int)f1, v2 = (int)f2;

        const float q00 = u1 * u2, q01 = u1 * w2, q10 = w1 * u2, q11 = w1 * w2;
        float wgt[8];
        wgt[0] = u0 * q00; wgt[1] = u0 * q01; wgt[2] = u0 * q10; wgt[3] = u0 * q11;
        wgt[4] = w0 * q00; wgt[5] = w0 * q01; wgt[6] = w0 * q10; wgt[7] = w0 * q11;

        int idx[8];
        if (dense) {
            const int bidx = (v0 * np1 + v1) * np1 + v2;
            const int sx = np1 * np1;
            idx[0] = bidx;            idx[1] = bidx + 1;
            idx[2] = bidx + np1;      idx[3] = bidx + np1 + 1;
            idx[4] = bidx + sx;       idx[5] = bidx + sx + 1;
            idx[6] = bidx + sx + np1; idx[7] = bidx + sx + np1 + 1;
        } else {
            const unsigned t1  = (unsigned)v1 * 2654435761u;
            const unsigned t1b = t1 + 2654435761u;
            const unsigned t2  = (unsigned)v2 * 805459861u;
            const unsigned t2b = t2 + 805459861u;
            const unsigned x0  = (unsigned)v0;
            const unsigned x0b = x0 + 1u;
            const unsigned m   = (unsigned)(T_SIZE - 1);
            idx[0] = (int)((x0  ^ t1  ^ t2 ) & m);
            idx[1] = (int)((x0  ^ t1  ^ t2b) & m);
            idx[2] = (int)((x0  ^ t1b ^ t2 ) & m);
            idx[3] = (int)((x0  ^ t1b ^ t2b) & m);
            idx[4] = (int)((x0b ^ t1  ^ t2 ) & m);
            idx[5] = (int)((x0b ^ t1  ^ t2b) & m);
            idx[6] = (int)((x0b ^ t1b ^ t2 ) & m);
            idx[7] = (int)((x0b ^ t1b ^ t2b) & m);
        }

        float acc0 = 0.0f, acc1 = 0.0f;
#pragma unroll
        for (int c = 0; c < 8; c++) {
            const float2 ft = stab[idx[c]];
            acc0 = fmaf(wgt[c], ft.x, acc0);
            acc1 = fmaf(wgt[c], ft.y, acc1);
        }

        featl[p] = make_float2(acc0, acc1);
    }
}

// ============================ Phase 2: MLP =================================
__global__ __launch_bounds__(P2_THREADS, 4)
void mlp_kernel(const float* __restrict__ x,
                const float* __restrict__ dW0, const float* __restrict__ db0,
                const float* __restrict__ dW1, const float* __restrict__ db1,
                const float* __restrict__ cW0, const float* __restrict__ cb0,
                const float* __restrict__ cW1, const float* __restrict__ cb1,
                const float* __restrict__ cW2, const float* __restrict__ cb2,
                float* __restrict__ out, int B)
{
    __shared__ alignas(16) float sW0 [32 * 64];
    __shared__ alignas(16) float sB0 [64];
    __shared__ alignas(16) float sW1 [64 * 16];
    __shared__ alignas(16) float sB1 [16];
    __shared__ alignas(16) float sC0W[20 * 64];
    __shared__ alignas(16) float sC0B[64];
    __shared__ alignas(16) float sC1Wt[64 * 64];   // transposed [j][k]
    __shared__ alignas(16) float sC1B[64];
    __shared__ alignas(16) float sC2W[64 * 4];
    __shared__ alignas(16) float sC2B[4];

    const int tid = threadIdx.x;
    for (int i = tid; i < 32 * 64; i += P2_THREADS) sW0[i]  = dW0[i];
    for (int i = tid; i < 64 * 16; i += P2_THREADS) sW1[i]  = dW1[i];
    for (int i = tid; i < 19 * 64; i += P2_THREADS) sC0W[i] = cW0[i];
    for (int i = tid; i < 64 * 64; i += P2_THREADS) {
        const int k = i >> 6, j = i & 63;
        sC1Wt[j * 64 + k] = cW1[i];
    }
    for (int i = tid; i < 64; i += P2_THREADS) {
        sB0[i]  = db0[i];
        sC0B[i] = cb0[i];
        sC1B[i] = cb1[i];
        sC2W[i * 4 + 0] = cW2[i * 3 + 0];
        sC2W[i * 4 + 1] = cW2[i * 3 + 1];
        sC2W[i * 4 + 2] = cW2[i * 3 + 2];
        sC2W[i * 4 + 3] = 0.0f;
    }
    if (tid < 16) sB1[tid]  = db1[tid];
    if (tid < 4)  sC2B[tid] = (tid < 3) ? cb2[tid] : 0.0f;
    __syncthreads();

    const int pt = blockIdx.x * P2_THREADS + tid;
    if (pt >= B) return;

    // ---- stage 0: h = db0 + sum_l feat_l @ dW0, packed f32x2 ----
    u64 hp[32];
#pragma unroll
    for (int j = 0; j < 16; j++) {
        const ulonglong2 b = lds128(&sB0[j * 4]);
        hp[2 * j] = b.x; hp[2 * j + 1] = b.y;
    }

    float2 f = __ldg(&g_feats[pt]);
#pragma unroll
    for (int l = 0; l < L_LEVELS; l++) {
        float2 nf;
        if (l + 1 < L_LEVELS) nf = __ldg(&g_feats[(size_t)(l + 1) * B + pt]);
        const u64 a0 = pack2(f.x, f.x);
        const u64 a1 = pack2(f.y, f.y);
        const float* r0 = &sW0[(2 * l) * 64];
        const float* r1 = &sW0[(2 * l + 1) * 64];
#pragma unroll
        for (int j = 0; j < 16; j++) {
            const ulonglong2 w0 = lds128(r0 + j * 4);
            const ulonglong2 w1 = lds128(r1 + j * 4);
            fma2(hp[2 * j],     a0, w0.x);
            fma2(hp[2 * j + 1], a0, w0.y);
            fma2(hp[2 * j],     a1, w1.x);
            fma2(hp[2 * j + 1], a1, w1.y);
        }
        f = nf;
    }

    // ---- layer 1: h2 = relu(h) @ dW1 + db1  (64 -> 16) ----
    u64 hq[8];
#pragma unroll
    for (int m = 0; m < 4; m++) {
        const ulonglong2 b = lds128(&sB1[m * 4]);
        hq[2 * m] = b.x; hq[2 * m + 1] = b.y;
    }
#pragma unroll
    for (int j2 = 0; j2 < 32; j2++) {
        const float2 v = unpack2(hp[j2]);
        const float r0 = fmaxf(v.x, 0.0f);
        const float r1 = fmaxf(v.y, 0.0f);
        const u64 p0 = pack2(r0, r0);
        const u64 p1 = pack2(r1, r1);
        const float* w0 = &sW1[(2 * j2) * 16];
        const float* w1 = &sW1[(2 * j2 + 1) * 16];
#pragma unroll
        for (int m = 0; m < 4; m++) {
            const ulonglong2 wa = lds128(w0 + m * 4);
            const ulonglong2 wb = lds128(w1 + m * 4);
            fma2(hq[2 * m],     p0, wa.x);
            fma2(hq[2 * m + 1], p0, wa.y);
            fma2(hq[2 * m],     p1, wb.x);
            fma2(hq[2 * m + 1], p1, wb.y);
        }
    }

    float h2[16];
#pragma unroll
    for (int m = 0; m < 8; m++) {
        const float2 v = unpack2(hq[m]);
        h2[2 * m] = v.x; h2[2 * m + 1] = v.y;
    }

    const float dens = sigmoidf_fast(h2[0]);

    // ---- cin = [density, relu(h2[1:16]), view] ----
    float cin[19];
    cin[0] = dens;
#pragma unroll
    for (int m = 1; m < 16; m++) cin[m] = fmaxf(h2[m], 0.0f);
    {
        const float2* xv = reinterpret_cast<const float2*>(x) + (size_t)pt * 3;
        const float2 b1 = __ldg(&xv[1]);
        const float2 b2 = __ldg(&xv[2]);
        cin[16] = b1.y; cin[17] = b2.x; cin[18] = b2.y;
    }

    // ---- c1 = relu(cin @ cW0 + cb0)  (19 -> 64) ----
    u64 c1p[32];
#pragma unroll
    for (int j = 0; j < 16; j++) {
        const ulonglong2 b = lds128(&sC0B[j * 4]);
        c1p[2 * j] = b.x; c1p[2 * j + 1] = b.y;
    }
#pragma unroll
    for (int k = 0; k < 19; k++) {
        const u64 c = pack2(cin[k], cin[k]);
        const float* wr = &sC0W[k * 64];
#pragma unroll
        for (int j = 0; j < 16; j++) {
            const ulonglong2 w = lds128(wr + j * 4);
            fma2(c1p[2 * j],     c, w.x);
            fma2(c1p[2 * j + 1], c, w.y);
        }
    }
#pragma unroll
    for (int j = 0; j < 32; j++) {
        const float2 v = unpack2(c1p[j]);
        c1p[j] = pack2(fmaxf(v.x, 0.0f), fmaxf(v.y, 0.0f));
    }

    // ---- c2 = relu(c1 @ cW1 + cb1) streamed into cW2 (64 -> 64 -> 3) ----
    float col0 = sC2B[0], col1 = sC2B[1], col2 = sC2B[2];
#pragma unroll 4
    for (int j = 0; j < 64; j++) {
        u64 ap = 0ULL;
        const float* wr = &sC1Wt[j * 64];
#pragma unroll
        for (int k = 0; k < 16; k++) {
            const ulonglong2 w = lds128(wr + k * 4);
            fma2(ap, c1p[2 * k],     w.x);
            fma2(ap, c1p[2 * k + 1], w.y);
        }
        const float2 v = unpack2(ap);
        const float a = fmaxf(sC1B[j] + v.x + v.y, 0.0f);
        const float4 w2v = *reinterpret_cast<const float4*>(&sC2W[j * 4]);
        col0 = fmaf(a, w2v.x, col0);
        col1 = fmaf(a, w2v.y, col1);
        col2 = fmaf(a, w2v.z, col2);
    }

    reinterpret_cast<float4*>(out)[pt] =
        make_float4(dens, sigmoidf_fast(col0), sigmoidf_fast(col1), sigmoidf_fast(col2));
}

} // anonymous namespace

extern "C" void kernel_launch(void* const* d_in, const int* in_sizes, int n_in,
                              void* d_out, int out_size)
{
    const float* x    = (const float*)d_in[0];
    const float* emb  = (const float*)d_in[1];
    const float* dW0  = (const float*)d_in[2];
    const float* db0  = (const float*)d_in[3];
    const float* dW1  = (const float*)d_in[4];
    const float* db1  = (const float*)d_in[5];
    const float* cW0  = (const float*)d_in[6];
    const float* cb0  = (const float*)d_in[7];
    const float* cW1  = (const float*)d_in[8];
    const float* cb1  = (const float*)d_in[9];
    const float* cW2  = (const float*)d_in[10];
    const float* cb2  = (const float*)d_in[11];
    float* out = (float*)d_out;

    const int B = in_sizes[0] / 6;

    NsParams nsp;
    const double g = exp((log(512.0) - log(16.0)) / 15.0);
    for (int i = 0; i < L_LEVELS; i++) {
        nsp.ns[i] = (int)(16.0 * pow(g, (double)i));
    }

    static bool attr_set = false;
    if (!attr_set) {
        cudaFuncSetAttribute(gather_kernel,
                             cudaFuncAttributeMaxDynamicSharedMemorySize,
                             T_SIZE * (int)sizeof(float2));
        attr_set = true;
    }

    const int nb1 = (B + P1_PTS_PER_BLOCK - 1) / P1_PTS_PER_BLOCK;
    dim3 grid1(nb1, L_LEVELS);
    gather_kernel<<<grid1, P1_THREADS, T_SIZE * sizeof(float2)>>>(x, emb, B, nsp);

    const int nb2 = (B + P2_THREADS - 1) / P2_THREADS;
    mlp_kernel<<<nb2, P2_THREADS>>>(x, dW0, db0, dW1, db1,
                                    cW0, cb0, cW1, cb1, cW2, cb2, out, B);
}

// round 7
// speedup vs baseline: 1.0280x; 1.0280x over previous
#include <cuda_runtime.h>
#include <math.h>
#include <stdint.h>

// ---------------------------------------------------------------------------
// Round 7: phase-2 MLP as a register-blocked SMEM GEMM.
//  CTA = 128 points. Activations ping-pong between two SMEM buffers laid out
//  [k][p] (rows of 128+4 f32). Each thread owns an 8pt x 8neuron f32x2
//  register tile: per k-step 4x LDS.128 feed 32 fma.rn.f32x2, so the fma
//  pipe (not L1) is the binding resource. Phase 1 gather unchanged.
// ---------------------------------------------------------------------------

namespace {

constexpr int L_LEVELS = 16;
constexpr int T_SIZE   = 16384;
constexpr int B_MAX    = 1 << 21;
constexpr int P1_THREADS = 1024;
constexpr int P1_PTS_PER_BLOCK = 16384;

constexpr int ROW = 132;          // floats per activation row (128 + 4 pad)

typedef unsigned long long u64;

struct NsParams { int ns[L_LEVELS]; };

__device__ float2 g_feats[(size_t)L_LEVELS * B_MAX];   // 256 MB scratch

// ---- SMEM layout (floats) for phase-2 dynamic shared buffer ----
constexpr int OFF_A   = 0;                   // bufA 64 x ROW
constexpr int OFF_B   = OFF_A + 64 * ROW;    // bufB 64 x ROW
constexpr int OFF_W0  = OFF_B + 64 * ROW;    // dW0  [32][64]
constexpr int OFF_W1  = OFF_W0 + 32 * 64;    // dW1  [64][16]
constexpr int OFF_C0W = OFF_W1 + 64 * 16;    // cW0  [20][64] (row 19 zero)
constexpr int OFF_C1W = OFF_C0W + 20 * 64;   // cW1  [64][64]
constexpr int OFF_C2W = OFF_C1W + 64 * 64;   // cW2  [64][4]  (col 3 zero)
constexpr int OFF_B0  = OFF_C2W + 64 * 4;    // 64
constexpr int OFF_B1  = OFF_B0 + 64;         // 16
constexpr int OFF_C0B = OFF_B1 + 16;         // 64
constexpr int OFF_C1B = OFF_C0B + 64;        // 64
constexpr int OFF_C2B = OFF_C1B + 64;        // 4
constexpr int OFF_DEN = OFF_C2B + 4;         // 128
constexpr int SMEM_FLOATS = OFF_DEN + 128;
constexpr int SMEM_BYTES  = SMEM_FLOATS * 4; // ~103.8 KB

__device__ __forceinline__ void fma2(u64& d, u64 a, u64 b) {
    asm("fma.rn.f32x2 %0, %1, %2, %0;" : "+l"(d) : "l"(a), "l"(b));
}
__device__ __forceinline__ u64 pack2(float lo, float hi) {
    u64 r; asm("mov.b64 %0, {%1, %2};" : "=l"(r) : "f"(lo), "f"(hi)); return r;
}
__device__ __forceinline__ float2 unpack2(u64 v) {
    float2 r; asm("mov.b64 {%0, %1}, %2;" : "=f"(r.x), "=f"(r.y) : "l"(v)); return r;
}
__device__ __forceinline__ u64 relu2(u64 v) {
    float2 t = unpack2(v);
    return pack2(fmaxf(t.x, 0.0f), fmaxf(t.y, 0.0f));
}
__device__ __forceinline__ float sigmoidf_fast(float v) {
    return 1.0f / (1.0f + __expf(-v));
}
__device__ __forceinline__ ulonglong2 lds128(const float* p) {
    ulonglong2 v;
    asm("ld.shared.v2.u64 {%0, %1}, [%2];"
        : "=l"(v.x), "=l"(v.y) : "l"(__cvta_generic_to_shared(p)));
    return v;
}
__device__ __forceinline__ u64 lds64(const float* p) {
    u64 v;
    asm("ld.shared.u64 %0, [%1];"
        : "=l"(v) : "l"(__cvta_generic_to_shared(p)));
    return v;
}
__device__ __forceinline__ void sts128(float* p, u64 a, u64 b) {
    asm volatile("st.shared.v2.u64 [%0], {%1, %2};"
                 :: "l"(__cvta_generic_to_shared(p)), "l"(a), "l"(b));
}

// ============================ Phase 1: gather ==============================
__global__ __launch_bounds__(P1_THREADS, 1)
void gather_kernel(const float* __restrict__ x,
                   const float* __restrict__ embed,
                   int B, NsParams nsp)
{
    extern __shared__ float2 stab[];   // T_SIZE float2 = 128 KB

    const int l = blockIdx.y;
    const int n = nsp.ns[l];
    const float nf = (float)n;
    const int np1 = n + 1;
    const bool dense = (np1 * np1 * np1 <= T_SIZE);

    {
        const float4* src = reinterpret_cast<const float4*>(embed) + (size_t)l * (T_SIZE / 2);
        float4* dst = reinterpret_cast<float4*>(stab);
        for (int i = threadIdx.x; i < T_SIZE / 2; i += P1_THREADS) dst[i] = src[i];
    }
    __syncthreads();

    const int base = blockIdx.x * P1_PTS_PER_BLOCK;
    const int end  = min(base + P1_PTS_PER_BLOCK, B);
    float2* featl = g_feats + (size_t)l * B;

    for (int p = base + threadIdx.x; p < end; p += P1_THREADS) {
        const float2* xv = reinterpret_cast<const float2*>(x) + (size_t)p * 3;
        const float2 a0 = __ldg(&xv[0]);
        const float2 a1 = __ldg(&xv[1]);

        float px = fminf(fmaxf((a0.x + 5.0f) * 0.1f, 0.0f), 0.999999f);
        float py = fminf(fmaxf((a0.y + 5.0f) * 0.1f, 0.0f), 0.999999f);
        float pz = fminf(fmaxf((a1.x + 5.0f) * 0.1f, 0.0f), 0.999999f);

        const float xl0 = px * nf, xl1 = py * nf, xl2 = pz * nf;
        const float f0 = floorf(xl0), f1 = floorf(xl1), f2 = floorf(xl2);
        const float w0 = xl0 - f0, w1 = xl1 - f1, w2 = xl2 - f2;
        const float u0 = 1.0f - w0, u1 = 1.0f - w1, u2 = 1.0f - w2;
        const int v0 = (int)f0, v1 = (int)f1, v2 = (int)f2;

        const float q00 = u1 * u2, q01 = u1 * w2, q10 = w1 * u2, q11 = w1 * w2;
        float wgt[8];
        wgt[0] = u0 * q00; wgt[1] = u0 * q01; wgt[2] = u0 * q10; wgt[3] = u0 * q11;
        wgt[4] = w0 * q00; wgt[5] = w0 * q01; wgt[6] = w0 * q10; wgt[7] = w0 * q11;

        int idx[8];
        if (dense) {
            const int bidx = (v0 * np1 + v1) * np1 + v2;
            const int sx = np1 * np1;
            idx[0] = bidx;            idx[1] = bidx + 1;
            idx[2] = bidx + np1;      idx[3] = bidx + np1 + 1;
            idx[4] = bidx + sx;       idx[5] = bidx + sx + 1;
            idx[6] = bidx + sx + np1; idx[7] = bidx + sx + np1 + 1;
        } else {
            const unsigned t1  = (unsigned)v1 * 2654435761u;
            const unsigned t1b = t1 + 2654435761u;
            const unsigned t2  = (unsigned)v2 * 805459861u;
            const unsigned t2b = t2 + 805459861u;
            const unsigned x0  = (unsigned)v0;
            const unsigned x0b = x0 + 1u;
            const unsigned m   = (unsigned)(T_SIZE - 1);
            idx[0] = (int)((x0  ^ t1  ^ t2 ) & m);
            idx[1] = (int)((x0  ^ t1  ^ t2b) & m);
            idx[2] = (int)((x0  ^ t1b ^ t2 ) & m);
            idx[3] = (int)((x0  ^ t1b ^ t2b) & m);
            idx[4] = (int)((x0b ^ t1  ^ t2 ) & m);
            idx[5] = (int)((x0b ^ t1  ^ t2b) & m);
            idx[6] = (int)((x0b ^ t1b ^ t2 ) & m);
            idx[7] = (int)((x0b ^ t1b ^ t2b) & m);
        }

        float acc0 = 0.0f, acc1 = 0.0f;
#pragma unroll
        for (int c = 0; c < 8; c++) {
            const float2 ft = stab[idx[c]];
            acc0 = fmaf(wgt[c], ft.x, acc0);
            acc1 = fmaf(wgt[c], ft.y, acc1);
        }

        featl[p] = make_float2(acc0, acc1);
    }
}

// ====================== Phase 2: GEMM-tiled MLP ============================

// 8pt x 8neuron register tile GEMM: Aout[n][p] = act(Ain @ W + bias)
// Thread (ng, pg): neurons n0=ng*8..+7, points {pA..pA+3, 64+pA..64+pA+3}.
template<int K, bool RELU>
__device__ __forceinline__ void gemm_tile(const float* Ain, const float* W,
                                          const float* bias, float* Aout,
                                          int pA, int n0)
{
    u64 acc[8][4];
#pragma unroll
    for (int j = 0; j < 8; j++) {
        const float b = bias[n0 + j];
        const u64 bp = pack2(b, b);
        acc[j][0] = bp; acc[j][1] = bp; acc[j][2] = bp; acc[j][3] = bp;
    }

#pragma unroll 4
    for (int k = 0; k < K; k++) {
        const float* ar = Ain + k * ROW;
        const ulonglong2 a01 = lds128(ar + pA);        // pts pA..pA+3
        const ulonglong2 a23 = lds128(ar + 64 + pA);   // pts 64+pA..+3
        const float* wr = W + k * 64 + n0;
        const ulonglong2 wv0 = lds128(wr);
        const ulonglong2 wv1 = lds128(wr + 4);
        const float2 w01 = unpack2(wv0.x);
        const float2 w23 = unpack2(wv0.y);
        const float2 w45 = unpack2(wv1.x);
        const float2 w67 = unpack2(wv1.y);
        const float wv[8] = {w01.x, w01.y, w23.x, w23.y, w45.x, w45.y, w67.x, w67.y};
#pragma unroll
        for (int j = 0; j < 8; j++) {
            const u64 wp = pack2(wv[j], wv[j]);
            fma2(acc[j][0], a01.x, wp);
            fma2(acc[j][1], a01.y, wp);
            fma2(acc[j][2], a23.x, wp);
            fma2(acc[j][3], a23.y, wp);
        }
    }

#pragma unroll
    for (int j = 0; j < 8; j++) {
        u64 v0 = acc[j][0], v1 = acc[j][1], v2 = acc[j][2], v3 = acc[j][3];
        if (RELU) { v0 = relu2(v0); v1 = relu2(v1); v2 = relu2(v2); v3 = relu2(v3); }
        float* orow = Aout + (n0 + j) * ROW;
        sts128(orow + pA, v0, v1);
        sts128(orow + 64 + pA, v2, v3);
    }
}

__global__ __launch_bounds__(128)
void mlp_kernel(const float* __restrict__ x,
                const float* __restrict__ dW0, const float* __restrict__ db0,
                const float* __restrict__ dW1, const float* __restrict__ db1,
                const float* __restrict__ cW0, const float* __restrict__ cb0,
                const float* __restrict__ cW1, const float* __restrict__ cb1,
                const float* __restrict__ cW2, const float* __restrict__ cb2,
                float* __restrict__ out, int B)
{
    extern __shared__ float sm[];
    float* bufA = sm + OFF_A;
    float* bufB = sm + OFF_B;
    float* sW0  = sm + OFF_W0;
    float* sW1  = sm + OFF_W1;
    float* sC0W = sm + OFF_C0W;
    float* sC1W = sm + OFF_C1W;
    float* sC2W = sm + OFF_C2W;
    float* sB0  = sm + OFF_B0;
    float* sB1  = sm + OFF_B1;
    float* sC0B = sm + OFF_C0B;
    float* sC1B = sm + OFF_C1B;
    float* sC2B = sm + OFF_C2B;
    float* sDen = sm + OFF_DEN;

    const int tid = threadIdx.x;
    const int pg  = tid & 15;
    const int ng  = tid >> 4;
    const int pA  = pg * 4;
    const int n0  = ng * 8;

    // ---- stage weights (k-major already) + biases ----
    for (int i = tid; i < 32 * 64; i += 128) sW0[i] = dW0[i];
    for (int i = tid; i < 64 * 16; i += 128) sW1[i] = dW1[i];
    for (int i = tid; i < 20 * 64; i += 128) sC0W[i] = (i < 19 * 64) ? cW0[i] : 0.0f;
    for (int i = tid; i < 64 * 64; i += 128) sC1W[i] = cW1[i];
    for (int i = tid; i < 64 * 4;  i += 128) {
        const int k = i >> 2, c = i & 3;
        sC2W[i] = (c < 3) ? cW2[k * 3 + c] : 0.0f;
    }
    if (tid < 64) { sB0[tid] = db0[tid]; sC0B[tid] = cb0[tid]; sC1B[tid] = cb1[tid]; }
    if (tid < 16) sB1[tid] = db1[tid];
    if (tid < 4)  sC2B[tid] = (tid < 3) ? cb2[tid] : 0.0f;

    const int cta_base = blockIdx.x * 128;
    const int ptg = cta_base + tid;
    const int pt  = (ptg < B) ? ptg : (B - 1);

    // ---- stage features into bufA rows 0..31, layout [k][p] ----
#pragma unroll
    for (int l = 0; l < L_LEVELS; l++) {
        const float2 f = __ldg(&g_feats[(size_t)l * B + pt]);
        bufA[(2 * l) * ROW + tid]     = f.x;
        bufA[(2 * l + 1) * ROW + tid] = f.y;
    }
    __syncthreads();

    // ---- L0: h = relu?(no) ... h = feats(32) @ dW0 + db0 -> relu, 64 wide ----
    gemm_tile<32, true>(bufA, sW0, sB0, bufB, pA, n0);
    __syncthreads();

    // ---- L1: h2 = relu(h)(64) @ dW1 + db1, N=16 (no relu), 2 neurons/thread ----
    {
        const int nn0 = ng * 2;   // neurons nn0, nn0+1
        u64 acc[2][4];
#pragma unroll
        for (int j = 0; j < 2; j++) {
            const float b = sB1[nn0 + j];
            const u64 bp = pack2(b, b);
            acc[j][0] = bp; acc[j][1] = bp; acc[j][2] = bp; acc[j][3] = bp;
        }
#pragma unroll 4
        for (int k = 0; k < 64; k++) {
            const float* ar = bufB + k * ROW;
            const ulonglong2 a01 = lds128(ar + pA);
            const ulonglong2 a23 = lds128(ar + 64 + pA);
            const float2 wpair = unpack2(lds64(sW1 + k * 16 + nn0));
            const u64 wp0 = pack2(wpair.x, wpair.x);
            const u64 wp1 = pack2(wpair.y, wpair.y);
            fma2(acc[0][0], a01.x, wp0); fma2(acc[0][1], a01.y, wp0);
            fma2(acc[0][2], a23.x, wp0); fma2(acc[0][3], a23.y, wp0);
            fma2(acc[1][0], a01.x, wp1); fma2(acc[1][1], a01.y, wp1);
            fma2(acc[1][2], a23.x, wp1); fma2(acc[1][3], a23.y, wp1);
        }
#pragma unroll
        for (int j = 0; j < 2; j++) {
            float* orow = bufA + (nn0 + j) * ROW;    // h2 rows 0..15 of bufA
            sts128(orow + pA, acc[j][0], acc[j][1]);
            sts128(orow + 64 + pA, acc[j][2], acc[j][3]);
        }
    }
    __syncthreads();

    // ---- cin stage (point-parallel): bufA rows 16..35 = [dens, relu(h2), view, 0] ----
    {
        float h2v[16];
#pragma unroll
        for (int m = 0; m < 16; m++) h2v[m] = bufA[m * ROW + tid];
        const float dens = sigmoidf_fast(h2v[0]);
        sDen[tid] = dens;
        bufA[16 * ROW + tid] = dens;
#pragma unroll
        for (int m = 1; m < 16; m++)
            bufA[(16 + m) * ROW + tid] = fmaxf(h2v[m], 0.0f);
        const float2* xv = reinterpret_cast<const float2*>(x) + (size_t)pt * 3;
        const float2 b1 = __ldg(&xv[1]);
        const float2 b2 = __ldg(&xv[2]);
        bufA[32 * ROW + tid] = b1.y;
        bufA[33 * ROW + tid] = b2.x;
        bufA[34 * ROW + tid] = b2.y;
        bufA[35 * ROW + tid] = 0.0f;
    }
    __syncthreads();

    // ---- L2: c1 = relu(cin(20) @ cW0 + cb0), 64 wide ----
    gemm_tile<20, true>(bufA + 16 * ROW, sC0W, sC0B, bufB, pA, n0);
    __syncthreads();

    // ---- L3: c2 = relu(c1(64) @ cW1 + cb1), 64 wide ----
    gemm_tile<64, true>(bufB, sC1W, sC1B, bufA, pA, n0);
    __syncthreads();

    // ---- L4 (point-parallel): color = sigmoid(c2(64) @ cW2 + cb2) ----
    {
        u64 c01 = pack2(sC2B[0], sC2B[1]);
        float c2a = sC2B[2];
#pragma unroll 8
        for (int k = 0; k < 64; k++) {
            const float a = bufA[k * ROW + tid];
            const ulonglong2 w = lds128(sC2W + k * 4);   // (w0,w1),(w2,pad)
            const u64 ap = pack2(a, a);
            fma2(c01, ap, w.x);
            c2a = fmaf(a, unpack2(w.y).x, c2a);
        }
        const float2 cc = unpack2(c01);
        if (ptg < B) {
            reinterpret_cast<float4*>(out)[ptg] =
                make_float4(sDen[tid], sigmoidf_fast(cc.x),
                            sigmoidf_fast(cc.y), sigmoidf_fast(c2a));
        }
    }
}

} // anonymous namespace

extern "C" void kernel_launch(void* const* d_in, const int* in_sizes, int n_in,
                              void* d_out, int out_size)
{
    const float* x    = (const float*)d_in[0];
    const float* emb  = (const float*)d_in[1];
    const float* dW0  = (const float*)d_in[2];
    const float* db0  = (const float*)d_in[3];
    const float* dW1  = (const float*)d_in[4];
    const float* db1  = (const float*)d_in[5];
    const float* cW0  = (const float*)d_in[6];
    const float* cb0  = (const float*)d_in[7];
    const float* cW1  = (const float*)d_in[8];
    const float* cb1  = (const float*)d_in[9];
    const float* cW2  = (const float*)d_in[10];
    const float* cb2  = (const float*)d_in[11];
    float* out = (float*)d_out;

    const int B = in_sizes[0] / 6;

    NsParams nsp;
    const double g = exp((log(512.0) - log(16.0)) / 15.0);
    for (int i = 0; i < L_LEVELS; i++) {
        nsp.ns[i] = (int)(16.0 * pow(g, (double)i));
    }

    static bool attr_set = false;
    if (!attr_set) {
        cudaFuncSetAttribute(gather_kernel,
                             cudaFuncAttributeMaxDynamicSharedMemorySize,
                             T_SIZE * (int)sizeof(float2));
        cudaFuncSetAttribute(mlp_kernel,
                             cudaFuncAttributeMaxDynamicSharedMemorySize,
                             SMEM_BYTES);
        attr_set = true;
    }

    const int nb1 = (B + P1_PTS_PER_BLOCK - 1) / P1_PTS_PER_BLOCK;
    dim3 grid1(nb1, L_LEVELS);
    gather_kernel<<<grid1, P1_THREADS, T_SIZE * sizeof(float2)>>>(x, emb, B, nsp);

    const int nb2 = (B + 127) / 128;
    mlp_kernel<<<nb2, 128, SMEM_BYTES>>>(x, dW0, db0, dW1, db1,
                                         cW0, cb0, cW1, cb1, cW2, cb2, out, B);
}

// round 8
// speedup vs baseline: 1.1709x; 1.1391x over previous
#include <cuda_runtime.h>
#include <math.h>
#include <stdint.h>

// ---------------------------------------------------------------------------
// Round 8: round-4 structure (2 pts/thread, sync-free MLP, broadcast LDS.128
// weights) + __launch_bounds__(128,3) to get 3 CTAs/SM (12 warps) instead of
// 2. L1(LDS) and FMA pipes both scale ~1.5x; L1 becomes the ~100% cap.
// ---------------------------------------------------------------------------

namespace {

constexpr int L_LEVELS = 16;
constexpr int T_SIZE   = 16384;
constexpr int B_MAX    = 1 << 21;
constexpr int P1_THREADS = 1024;
constexpr int P1_PTS_PER_BLOCK = 16384;
constexpr int P2_THREADS = 128;
constexpr int P2_PTS_PER_THREAD = 2;

typedef unsigned long long u64;

struct NsParams { int ns[L_LEVELS]; };

__device__ float2 g_feats[(size_t)L_LEVELS * B_MAX];   // 256 MB scratch

__device__ __forceinline__ void fma2(u64& d, u64 a, u64 b) {
    asm("fma.rn.f32x2 %0, %1, %2, %0;" : "+l"(d) : "l"(a), "l"(b));
}
__device__ __forceinline__ u64 pack2(float lo, float hi) {
    u64 r; asm("mov.b64 %0, {%1, %2};" : "=l"(r) : "f"(lo), "f"(hi)); return r;
}
__device__ __forceinline__ float2 unpack2(u64 v) {
    float2 r; asm("mov.b64 {%0, %1}, %2;" : "=f"(r.x), "=f"(r.y) : "l"(v)); return r;
}
__device__ __forceinline__ float sigmoidf_fast(float v) {
    return 1.0f / (1.0f + __expf(-v));
}
__device__ __forceinline__ ulonglong2 lds128(const float* p) {
    ulonglong2 v;
    asm("ld.shared.v2.u64 {%0, %1}, [%2];"
        : "=l"(v.x), "=l"(v.y) : "l"(__cvta_generic_to_shared(p)));
    return v;
}

// ============================ Phase 1: gather ==============================
__global__ __launch_bounds__(P1_THREADS, 1)
void gather_kernel(const float* __restrict__ x,
                   const float* __restrict__ embed,
                   int B, NsParams nsp)
{
    extern __shared__ float2 stab[];   // T_SIZE float2 = 128 KB

    const int l = blockIdx.y;
    const int n = nsp.ns[l];
    const float nf = (float)n;
    const int np1 = n + 1;
    const bool dense = (np1 * np1 * np1 <= T_SIZE);

    {
        const float4* src = reinterpret_cast<const float4*>(embed) + (size_t)l * (T_SIZE / 2);
        float4* dst = reinterpret_cast<float4*>(stab);
        for (int i = threadIdx.x; i < T_SIZE / 2; i += P1_THREADS) dst[i] = src[i];
    }
    __syncthreads();

    const int base = blockIdx.x * P1_PTS_PER_BLOCK;
    const int end  = min(base + P1_PTS_PER_BLOCK, B);
    float2* featl = g_feats + (size_t)l * B;

    for (int p = base + threadIdx.x; p < end; p += P1_THREADS) {
        const float2* xv = reinterpret_cast<const float2*>(x) + (size_t)p * 3;
        const float2 a0 = __ldg(&xv[0]);
        const float2 a1 = __ldg(&xv[1]);

        float px = fminf(fmaxf((a0.x + 5.0f) * 0.1f, 0.0f), 0.999999f);
        float py = fminf(fmaxf((a0.y + 5.0f) * 0.1f, 0.0f), 0.999999f);
        float pz = fminf(fmaxf((a1.x + 5.0f) * 0.1f, 0.0f), 0.999999f);

        const float xl0 = px * nf, xl1 = py * nf, xl2 = pz * nf;
        const float f0 = floorf(xl0), f1 = floorf(xl1), f2 = floorf(xl2);
        const float w0 = xl0 - f0, w1 = xl1 - f1, w2 = xl2 - f2;
        const float u0 = 1.0f - w0, u1 = 1.0f - w1, u2 = 1.0f - w2;
        const int v0 = (int)f0, v1 = (int)f1, v2 = (int)f2;

        const float q00 = u1 * u2, q01 = u1 * w2, q10 = w1 * u2, q11 = w1 * w2;
        float wgt[8];
        wgt[0] = u0 * q00; wgt[1] = u0 * q01; wgt[2] = u0 * q10; wgt[3] = u0 * q11;
        wgt[4] = w0 * q00; wgt[5] = w0 * q01; wgt[6] = w0 * q10; wgt[7] = w0 * q11;

        int idx[8];
        if (dense) {
            const int bidx = (v0 * np1 + v1) * np1 + v2;
            const int sx = np1 * np1;
            idx[0] = bidx;            idx[1] = bidx + 1;
            idx[2] = bidx + np1;      idx[3] = bidx + np1 + 1;
            idx[4] = bidx + sx;       idx[5] = bidx + sx + 1;
            idx[6] = bidx + sx + np1; idx[7] = bidx + sx + np1 + 1;
        } else {
            const unsigned t1  = (unsigned)v1 * 2654435761u;
            const unsigned t1b = t1 + 2654435761u;
            const unsigned t2  = (unsigned)v2 * 805459861u;
            const unsigned t2b = t2 + 805459861u;
            const unsigned x0  = (unsigned)v0;
            const unsigned x0b = x0 + 1u;
            const unsigned m   = (unsigned)(T_SIZE - 1);
            idx[0] = (int)((x0  ^ t1  ^ t2 ) & m);
            idx[1] = (int)((x0  ^ t1  ^ t2b) & m);
            idx[2] = (int)((x0  ^ t1b ^ t2 ) & m);
            idx[3] = (int)((x0  ^ t1b ^ t2b) & m);
            idx[4] = (int)((x0b ^ t1  ^ t2 ) & m);
            idx[5] = (int)((x0b ^ t1  ^ t2b) & m);
            idx[6] = (int)((x0b ^ t1b ^ t2 ) & m);
            idx[7] = (int)((x0b ^ t1b ^ t2b) & m);
        }

        float acc0 = 0.0f, acc1 = 0.0f;
#pragma unroll
        for (int c = 0; c < 8; c++) {
            const float2 ft = stab[idx[c]];
            acc0 = fmaf(wgt[c], ft.x, acc0);
            acc1 = fmaf(wgt[c], ft.y, acc1);
        }

        featl[p] = make_float2(acc0, acc1);
    }
}

// ============================ Phase 2: MLP =================================
__global__ __launch_bounds__(P2_THREADS, 3)
void mlp_kernel(const float* __restrict__ x,
                const float* __restrict__ dW0, const float* __restrict__ db0,
                const float* __restrict__ dW1, const float* __restrict__ db1,
                const float* __restrict__ cW0, const float* __restrict__ cb0,
                const float* __restrict__ cW1, const float* __restrict__ cb1,
                const float* __restrict__ cW2, const float* __restrict__ cb2,
                float* __restrict__ out, int B)
{
    __shared__ alignas(16) float sW0 [32 * 64];
    __shared__ alignas(16) float sB0 [64];
    __shared__ alignas(16) float sW1 [64 * 16];
    __shared__ alignas(16) float sB1 [16];
    __shared__ alignas(16) float sC0W[20 * 64];
    __shared__ alignas(16) float sC0B[64];
    __shared__ alignas(16) float sC1Wt[64 * 64];   // transposed [j][k]
    __shared__ alignas(16) float sC1B[64];
    __shared__ alignas(16) float sC2W[64 * 4];
    __shared__ alignas(16) float sC2B[4];

    const int tid = threadIdx.x;
    for (int i = tid; i < 32 * 64; i += P2_THREADS) sW0[i]  = dW0[i];
    for (int i = tid; i < 64 * 16; i += P2_THREADS) sW1[i]  = dW1[i];
    for (int i = tid; i < 19 * 64; i += P2_THREADS) sC0W[i] = cW0[i];
    for (int i = tid; i < 64 * 64; i += P2_THREADS) {
        const int k = i >> 6, j = i & 63;
        sC1Wt[j * 64 + k] = cW1[i];
    }
    for (int i = tid; i < 64; i += P2_THREADS) {
        sB0[i]  = db0[i];
        sC0B[i] = cb0[i];
        sC1B[i] = cb1[i];
        sC2W[i * 4 + 0] = cW2[i * 3 + 0];
        sC2W[i * 4 + 1] = cW2[i * 3 + 1];
        sC2W[i * 4 + 2] = cW2[i * 3 + 2];
        sC2W[i * 4 + 3] = 0.0f;
    }
    if (tid < 16) sB1[tid]  = db1[tid];
    if (tid < 4)  sC2B[tid] = (tid < 3) ? cb2[tid] : 0.0f;
    __syncthreads();

    const int pbase = blockIdx.x * (P2_THREADS * P2_PTS_PER_THREAD) + tid;
    int pt[2];
    pt[0] = pbase;
    pt[1] = pbase + P2_THREADS;
    const bool ok1 = pt[1] < B;
    if (pt[0] >= B) return;
    if (!ok1) pt[1] = pt[0];

    // ---- stage 0: h = db0 + sum_l feat_l @ dW0, packed, 2-pt ILP ----
    u64 hp0[32], hp1[32];
#pragma unroll
    for (int j = 0; j < 16; j++) {
        const ulonglong2 b = lds128(&sB0[j * 4]);
        hp0[2 * j] = b.x; hp0[2 * j + 1] = b.y;
        hp1[2 * j] = b.x; hp1[2 * j + 1] = b.y;
    }

    float2 f0 = __ldg(&g_feats[pt[0]]);
    float2 f1 = __ldg(&g_feats[pt[1]]);
#pragma unroll
    for (int l = 0; l < L_LEVELS; l++) {
        float2 nf0, nf1;
        if (l + 1 < L_LEVELS) {
            nf0 = __ldg(&g_feats[(size_t)(l + 1) * B + pt[0]]);
            nf1 = __ldg(&g_feats[(size_t)(l + 1) * B + pt[1]]);
        }
        const u64 a00 = pack2(f0.x, f0.x), a01 = pack2(f0.y, f0.y);
        const u64 a10 = pack2(f1.x, f1.x), a11 = pack2(f1.y, f1.y);
        const float* r0 = &sW0[(2 * l) * 64];
        const float* r1 = &sW0[(2 * l + 1) * 64];
#pragma unroll
        for (int j = 0; j < 16; j++) {
            const ulonglong2 w0 = lds128(r0 + j * 4);
            const ulonglong2 w1 = lds128(r1 + j * 4);
            fma2(hp0[2 * j],     a00, w0.x);
            fma2(hp0[2 * j + 1], a00, w0.y);
            fma2(hp1[2 * j],     a10, w0.x);
            fma2(hp1[2 * j + 1], a10, w0.y);
            fma2(hp0[2 * j],     a01, w1.x);
            fma2(hp0[2 * j + 1], a01, w1.y);
            fma2(hp1[2 * j],     a11, w1.x);
            fma2(hp1[2 * j + 1], a11, w1.y);
        }
        f0 = nf0; f1 = nf1;
    }

    // ---- layer 1: h2 = relu(h) @ dW1 + db1  (64 -> 16) ----
    u64 hq0[8], hq1[8];
#pragma unroll
    for (int m = 0; m < 4; m++) {
        const ulonglong2 b = lds128(&sB1[m * 4]);
        hq0[2 * m] = b.x; hq0[2 * m + 1] = b.y;
        hq1[2 * m] = b.x; hq1[2 * m + 1] = b.y;
    }
#pragma unroll
    for (int j2 = 0; j2 < 32; j2++) {
        const float2 v0 = unpack2(hp0[j2]);
        const float2 v1 = unpack2(hp1[j2]);
        const float r00 = fmaxf(v0.x, 0.0f), r01 = fmaxf(v0.y, 0.0f);
        const float r10 = fmaxf(v1.x, 0.0f), r11 = fmaxf(v1.y, 0.0f);
        const u64 p00 = pack2(r00, r00);
        const u64 p01 = pack2(r01, r01);
        const u64 p10 = pack2(r10, r10);
        const u64 p11 = pack2(r11, r11);
        const float* w0 = &sW1[(2 * j2) * 16];
        const float* w1 = &sW1[(2 * j2 + 1) * 16];
#pragma unroll
        for (int m = 0; m < 4; m++) {
            const ulonglong2 wa = lds128(w0 + m * 4);
            const ulonglong2 wb = lds128(w1 + m * 4);
            fma2(hq0[2 * m],     p00, wa.x);
            fma2(hq0[2 * m + 1], p00, wa.y);
            fma2(hq1[2 * m],     p10, wa.x);
            fma2(hq1[2 * m + 1], p10, wa.y);
            fma2(hq0[2 * m],     p01, wb.x);
            fma2(hq0[2 * m + 1], p01, wb.y);
            fma2(hq1[2 * m],     p11, wb.x);
            fma2(hq1[2 * m + 1], p11, wb.y);
        }
    }

    float h2a[16], h2b[16];
#pragma unroll
    for (int m = 0; m < 8; m++) {
        const float2 va = unpack2(hq0[m]);
        const float2 vb = unpack2(hq1[m]);
        h2a[2 * m] = va.x; h2a[2 * m + 1] = va.y;
        h2b[2 * m] = vb.x; h2b[2 * m + 1] = vb.y;
    }

    const float dens0 = sigmoidf_fast(h2a[0]);
    const float dens1 = sigmoidf_fast(h2b[0]);

    // ---- cin = [density, relu(h2[1:16]), view] ----
    float cina[19], cinb[19];
    cina[0] = dens0; cinb[0] = dens1;
#pragma unroll
    for (int m = 1; m < 16; m++) {
        cina[m] = fmaxf(h2a[m], 0.0f);
        cinb[m] = fmaxf(h2b[m], 0.0f);
    }
    {
        const float2* xv0 = reinterpret_cast<const float2*>(x) + (size_t)pt[0] * 3;
        const float2* xv1 = reinterpret_cast<const float2*>(x) + (size_t)pt[1] * 3;
        const float2 b1a = __ldg(&xv0[1]); const float2 b2a = __ldg(&xv0[2]);
        const float2 b1b = __ldg(&xv1[1]); const float2 b2b = __ldg(&xv1[2]);
        cina[16] = b1a.y; cina[17] = b2a.x; cina[18] = b2a.y;
        cinb[16] = b1b.y; cinb[17] = b2b.x; cinb[18] = b2b.y;
    }

    // ---- c1 = relu(cin @ cW0 + cb0)  (19 -> 64) ----
    u64 c1p0[32], c1p1[32];
#pragma unroll
    for (int j = 0; j < 16; j++) {
        const ulonglong2 b = lds128(&sC0B[j * 4]);
        c1p0[2 * j] = b.x; c1p0[2 * j + 1] = b.y;
        c1p1[2 * j] = b.x; c1p1[2 * j + 1] = b.y;
    }
#pragma unroll
    for (int k = 0; k < 19; k++) {
        const u64 ca = pack2(cina[k], cina[k]);
        const u64 cb = pack2(cinb[k], cinb[k]);
        const float* wr = &sC0W[k * 64];
#pragma unroll
        for (int j = 0; j < 16; j++) {
            const ulonglong2 w = lds128(wr + j * 4);
            fma2(c1p0[2 * j],     ca, w.x);
            fma2(c1p0[2 * j + 1], ca, w.y);
            fma2(c1p1[2 * j],     cb, w.x);
            fma2(c1p1[2 * j + 1], cb, w.y);
        }
    }
#pragma unroll
    for (int j = 0; j < 32; j++) {
        float2 va = unpack2(c1p0[j]);
        float2 vb = unpack2(c1p1[j]);
        c1p0[j] = pack2(fmaxf(va.x, 0.0f), fmaxf(va.y, 0.0f));
        c1p1[j] = pack2(fmaxf(vb.x, 0.0f), fmaxf(vb.y, 0.0f));
    }

    // ---- c2 = relu(c1 @ cW1 + cb1) streamed into cW2 (64 -> 64 -> 3) ----
    float col[2][3];
    col[0][0] = sC2B[0]; col[0][1] = sC2B[1]; col[0][2] = sC2B[2];
    col[1][0] = sC2B[0]; col[1][1] = sC2B[1]; col[1][2] = sC2B[2];
#pragma unroll 4
    for (int j = 0; j < 64; j++) {
        u64 apa = 0ULL, apb = 0ULL;
        const float* wr = &sC1Wt[j * 64];
#pragma unroll
        for (int k = 0; k < 16; k++) {
            const ulonglong2 w = lds128(wr + k * 4);
            fma2(apa, c1p0[2 * k],     w.x);
            fma2(apa, c1p0[2 * k + 1], w.y);
            fma2(apb, c1p1[2 * k],     w.x);
            fma2(apb, c1p1[2 * k + 1], w.y);
        }
        const float2 va = unpack2(apa);
        const float2 vb = unpack2(apb);
        const float bias = sC1B[j];
        float aa = fmaxf(bias + va.x + va.y, 0.0f);
        float ab = fmaxf(bias + vb.x + vb.y, 0.0f);
        const float4 w2v = *reinterpret_cast<const float4*>(&sC2W[j * 4]);
        col[0][0] = fmaf(aa, w2v.x, col[0][0]);
        col[0][1] = fmaf(aa, w2v.y, col[0][1]);
        col[0][2] = fmaf(aa, w2v.z, col[0][2]);
        col[1][0] = fmaf(ab, w2v.x, col[1][0]);
        col[1][1] = fmaf(ab, w2v.y, col[1][1]);
        col[1][2] = fmaf(ab, w2v.z, col[1][2]);
    }

    reinterpret_cast<float4*>(out)[pt[0]] =
        make_float4(dens0, sigmoidf_fast(col[0][0]), sigmoidf_fast(col[0][1]), sigmoidf_fast(col[0][2]));
    if (ok1) {
        reinterpret_cast<float4*>(out)[pt[1]] =
            make_float4(dens1, sigmoidf_fast(col[1][0]), sigmoidf_fast(col[1][1]), sigmoidf_fast(col[1][2]));
    }
}

} // anonymous namespace

extern "C" void kernel_launch(void* const* d_in, const int* in_sizes, int n_in,
                              void* d_out, int out_size)
{
    const float* x    = (const float*)d_in[0];
    const float* emb  = (const float*)d_in[1];
    const float* dW0  = (const float*)d_in[2];
    const float* db0  = (const float*)d_in[3];
    const float* dW1  = (const float*)d_in[4];
    const float* db1  = (const float*)d_in[5];
    const float* cW0  = (const float*)d_in[6];
    const float* cb0  = (const float*)d_in[7];
    const float* cW1  = (const float*)d_in[8];
    const float* cb1  = (const float*)d_in[9];
    const float* cW2  = (const float*)d_in[10];
    const float* cb2  = (const float*)d_in[11];
    float* out = (float*)d_out;

    const int B = in_sizes[0] / 6;

    NsParams nsp;
    const double g = exp((log(512.0) - log(16.0)) / 15.0);
    for (int i = 0; i < L_LEVELS; i++) {
        nsp.ns[i] = (int)(16.0 * pow(g, (double)i));
    }

    static bool attr_set = false;
    if (!attr_set) {
        cudaFuncSetAttribute(gather_kernel,
                             cudaFuncAttributeMaxDynamicSharedMemorySize,
                             T_SIZE * (int)sizeof(float2));
        attr_set = true;
    }

    const int nb1 = (B + P1_PTS_PER_BLOCK - 1) / P1_PTS_PER_BLOCK;
    dim3 grid1(nb1, L_LEVELS);
    gather_kernel<<<grid1, P1_THREADS, T_SIZE * sizeof(float2)>>>(x, emb, B, nsp);

    const int ptsPerBlock2 = P2_THREADS * P2_PTS_PER_THREAD;
    const int nb2 = (B + ptsPerBlock2 - 1) / ptsPerBlock2;
    mlp_kernel<<<nb2, P2_THREADS>>>(x, dW0, db0, dW1, db1,
                                    cW0, cb0, cW1, cb1, cW2, cb2, out, B);
}